// round 4
// baseline (speedup 1.0000x reference)
#include <cuda_runtime.h>

// GRU_39170101739852: B=4096, T=512, H=64 GRU + Linear(H->1), fp32.
// R4: W_hh lives in REGISTERS (thread = unit u x k-chunk c, 16 k each).
// Per-step LDS is h-only (broadcast LDS.128). k-chunk partials combined with
// a slot-permuted xor-shuffle reduction (compile-time register indices).

#define BB 4096
#define TT 512
#define HH 64
#define MB 16
#define NTHREADS 256
#define TCHUNK 32
#define PITCH_H 68      // h row pitch (16B-aligned, c-addresses bank-disjoint)
#define PITCH_X 33

typedef unsigned long long u64;

__device__ __forceinline__ u64 pack2(float lo, float hi) {
    u64 r; asm("mov.b64 %0, {%1,%2};" : "=l"(r) : "f"(lo), "f"(hi)); return r;
}
__device__ __forceinline__ void unpack2(u64 v, float &lo, float &hi) {
    asm("mov.b64 {%0,%1}, %2;" : "=f"(lo), "=f"(hi) : "l"(v));
}
__device__ __forceinline__ void fma2(u64 &d, u64 a, u64 b) {
    asm("fma.rn.f32x2 %0, %1, %2, %0;" : "+l"(d) : "l"(a), "l"(b));
}
__device__ __forceinline__ void add2(u64 &d, u64 a) {
    asm("add.rn.f32x2 %0, %0, %1;" : "+l"(d) : "l"(a));
}
__device__ __forceinline__ float hsum2(u64 v) {
    float lo, hi; unpack2(v, lo, hi); return lo + hi;
}
__device__ __forceinline__ u64 shflx64(u64 v, int m) {
    float lo, hi; unpack2(v, lo, hi);
    lo = __shfl_xor_sync(0xffffffffu, lo, m);
    hi = __shfl_xor_sync(0xffffffffu, hi, m);
    return pack2(lo, hi);
}
__device__ __forceinline__ float fsig(float v) {
    float e; asm("ex2.approx.f32 %0, %1;" : "=f"(e) : "f"(v * -1.4426950408889634f));
    float r; asm("rcp.approx.f32 %0, %1;" : "=f"(r) : "f"(1.0f + e));
    return r;
}
__device__ __forceinline__ float ftanh(float v) {
    return fmaf(2.0f, fsig(2.0f * v), -1.0f);
}

// Shared layout (floats):
//   hA  : [0, 1088)        h buffer 0: h[b*68 + k]
//   hB  : [1088, 2176)     h buffer 1
//   xt  : [2176, +1056)    x tiles, 2 bufs of 16x33
//   red : [3232, +256)     out partials, 2 bufs of 16x8: red[buf*128 + j*8 + w]
#define OFF_HA 0
#define OFF_HB 1088
#define OFF_X  2176
#define OFF_R  3232
#define SMEM_FLOATS 3488

__global__ void __launch_bounds__(NTHREADS, 2)
gru_kernel(const float* __restrict__ x,
           const float* __restrict__ w_ih,
           const float* __restrict__ w_hh,
           const float* __restrict__ b_ih,
           const float* __restrict__ b_hh,
           const float* __restrict__ w_lin,
           const float* __restrict__ b_lin,
           float* __restrict__ out)
{
    extern __shared__ float smem[];
    float* hA  = smem + OFF_HA;
    float* hB  = smem + OFF_HB;
    float* xt  = smem + OFF_X;
    float* red = smem + OFF_R;

    const int tid = threadIdx.x;
    const int u   = tid >> 2;        // hidden unit 0..63
    const int c   = tid & 3;         // k-chunk: k in [16c, 16c+16)
    const int w   = tid >> 5;        // warp id
    const int bg  = blockIdx.x * MB;

    // ---- weights into registers: 3 gates x 8 k-pairs ----
    u64 wr2[8], wz2[8], wn2[8];
    {
        const int kb = 16 * c;
        const ulonglong2* pr = reinterpret_cast<const ulonglong2*>(&w_hh[(0 * HH + u) * HH + kb]);
        const ulonglong2* pz = reinterpret_cast<const ulonglong2*>(&w_hh[(1 * HH + u) * HH + kb]);
        const ulonglong2* pn = reinterpret_cast<const ulonglong2*>(&w_hh[(2 * HH + u) * HH + kb]);
        #pragma unroll
        for (int i = 0; i < 4; ++i) {
            ulonglong2 a = pr[i]; wr2[2*i] = a.x; wr2[2*i+1] = a.y;
            ulonglong2 b = pz[i]; wz2[2*i] = b.x; wz2[2*i+1] = b.y;
            ulonglong2 d = pn[i]; wn2[2*i] = d.x; wn2[2*i+1] = d.y;
        }
    }

    for (int i = tid; i < 2 * 1088; i += NTHREADS) hA[i] = 0.0f;  // zeros hA+hB

    // Stage first x chunk: 16 rows x 32 t
    if (tid < 128) {
        int bl = tid >> 3, q = tid & 7;
        float4 v = *reinterpret_cast<const float4*>(&x[(size_t)(bg + bl) * TT + q * 4]);
        xt[bl * PITCH_X + q * 4 + 0] = v.x;
        xt[bl * PITCH_X + q * 4 + 1] = v.y;
        xt[bl * PITCH_X + q * 4 + 2] = v.z;
        xt[bl * PITCH_X + q * 4 + 3] = v.w;
    }

    const float wir = w_ih[u], wiz = w_ih[HH + u], win = w_ih[2 * HH + u];
    const float brc = b_ih[u]        + b_hh[u];
    const float bzc = b_ih[HH + u]   + b_hh[HH + u];
    const float bin = b_ih[2 * HH + u];
    const float bhn = b_hh[2 * HH + u];
    const float wlu = w_lin[u];
    const float blv = b_lin[0];

    // Per-slot h row offsets: slot s reads batch (c^s) within the group.
    const int rowoff0 = (c ^ 0) * PITCH_H + 16 * c;
    const int rowoff1 = (c ^ 1) * PITCH_H + 16 * c;
    const int rowoff2 = (c ^ 2) * PITCH_H + 16 * c;
    const int rowoff3 = (c ^ 3) * PITCH_H + 16 * c;

    float hp[4];   // h_prev for this lane's batch in each group (j = g*4 + c)
    #pragma unroll
    for (int g = 0; g < 4; ++g) hp[g] = 0.0f;

    __syncthreads();

    int p = 0;
    for (int t = 0; t < TT; ++t) {
        const float* hr = p ? hB : hA;
        float*       hw = p ? hA : hB;
        const int   ttl  = t & (TCHUNK - 1);
        const float* xcur = xt + ((t >> 5) & 1) * (MB * PITCH_X);
        float* rcur = red + (t & 1) * 128;

        #pragma unroll
        for (int g = 0; g < 4; ++g) {
            const float* hg0 = hr + g * (4 * PITCH_H) + rowoff0;
            const float* hg1 = hr + g * (4 * PITCH_H) + rowoff1;
            const float* hg2 = hr + g * (4 * PITCH_H) + rowoff2;
            const float* hg3 = hr + g * (4 * PITCH_H) + rowoff3;

            u64 ar[4], az[4], an[4];
            #pragma unroll
            for (int s = 0; s < 4; ++s) { ar[s] = 0ull; az[s] = 0ull; an[s] = 0ull; }

            #pragma unroll
            for (int q = 0; q < 4; ++q) {
                ulonglong2 h0 = *reinterpret_cast<const ulonglong2*>(hg0 + 4 * q);
                ulonglong2 h1 = *reinterpret_cast<const ulonglong2*>(hg1 + 4 * q);
                ulonglong2 h2 = *reinterpret_cast<const ulonglong2*>(hg2 + 4 * q);
                ulonglong2 h3 = *reinterpret_cast<const ulonglong2*>(hg3 + 4 * q);
                const u64 wa = wr2[2*q], wb = wr2[2*q+1];
                const u64 za = wz2[2*q], zb = wz2[2*q+1];
                const u64 na = wn2[2*q], nb = wn2[2*q+1];
                fma2(ar[0], wa, h0.x); fma2(ar[0], wb, h0.y);
                fma2(az[0], za, h0.x); fma2(az[0], zb, h0.y);
                fma2(an[0], na, h0.x); fma2(an[0], nb, h0.y);
                fma2(ar[1], wa, h1.x); fma2(ar[1], wb, h1.y);
                fma2(az[1], za, h1.x); fma2(az[1], zb, h1.y);
                fma2(an[1], na, h1.x); fma2(an[1], nb, h1.y);
                fma2(ar[2], wa, h2.x); fma2(ar[2], wb, h2.y);
                fma2(az[2], za, h2.x); fma2(az[2], zb, h2.y);
                fma2(an[2], na, h2.x); fma2(an[2], nb, h2.y);
                fma2(ar[3], wa, h3.x); fma2(ar[3], wb, h3.y);
                fma2(az[3], za, h3.x); fma2(az[3], zb, h3.y);
                fma2(an[3], na, h3.x); fma2(an[3], nb, h3.y);
            }

            // c-chunk reduction: slot s of lane (c^s) holds my batch's chunk.
            add2(ar[0], shflx64(ar[1], 1)); add2(az[0], shflx64(az[1], 1)); add2(an[0], shflx64(an[1], 1));
            add2(ar[0], shflx64(ar[2], 2)); add2(az[0], shflx64(az[2], 2)); add2(an[0], shflx64(an[2], 2));
            add2(ar[0], shflx64(ar[3], 3)); add2(az[0], shflx64(az[3], 3)); add2(an[0], shflx64(an[3], 3));

            const int j = g * 4 + c;     // this lane's batch
            const float rs = hsum2(ar[0]);
            const float zs = hsum2(az[0]);
            const float ns = hsum2(an[0]);
            const float xv = xcur[j * PITCH_X + ttl];
            const float r  = fsig(fmaf(wir, xv, rs + brc));
            const float z  = fsig(fmaf(wiz, xv, zs + bzc));
            const float n  = ftanh(fmaf(r, ns + bhn, fmaf(win, xv, bin)));
            const float hn = fmaf(z, hp[g] - n, n);
            hp[g] = hn;
            hw[j * PITCH_H + u] = hn;

            // output partial: reduce over the 8 units of this warp
            float sv = wlu * hn;
            sv += __shfl_xor_sync(0xffffffffu, sv, 4);
            sv += __shfl_xor_sync(0xffffffffu, sv, 8);
            sv += __shfl_xor_sync(0xffffffffu, sv, 16);
            if ((tid & 31) < 4) rcur[j * 8 + w] = sv;
        }

        // Stage next x chunk before the barrier
        if (((t + 1) & (TCHUNK - 1)) == 0 && (t + 1) < TT && tid < 128) {
            int bl = tid >> 3, q = tid & 7;
            float4 v = *reinterpret_cast<const float4*>(
                &x[(size_t)(bg + bl) * TT + (t + 1) + q * 4]);
            float* xnext = xt + (((t + 1) >> 5) & 1) * (MB * PITCH_X);
            xnext[bl * PITCH_X + q * 4 + 0] = v.x;
            xnext[bl * PITCH_X + q * 4 + 1] = v.y;
            xnext[bl * PITCH_X + q * 4 + 2] = v.z;
            xnext[bl * PITCH_X + q * 4 + 3] = v.w;
        }

        __syncthreads();

        if (tid < MB) {
            const float4 r0 = *reinterpret_cast<const float4*>(&rcur[tid * 8]);
            const float4 r1 = *reinterpret_cast<const float4*>(&rcur[tid * 8 + 4]);
            out[(size_t)(bg + tid) * TT + t] =
                ((r0.x + r0.y) + (r0.z + r0.w)) +
                ((r1.x + r1.y) + (r1.z + r1.w)) + blv;
        }
        p ^= 1;
    }
}

extern "C" void kernel_launch(void* const* d_in, const int* in_sizes, int n_in,
                              void* d_out, int out_size) {
    const float* x     = (const float*)d_in[0];
    const float* w_ih  = (const float*)d_in[1];
    const float* w_hh  = (const float*)d_in[2];
    const float* b_ih  = (const float*)d_in[3];
    const float* b_hh  = (const float*)d_in[4];
    const float* w_lin = (const float*)d_in[5];
    const float* b_lin = (const float*)d_in[6];
    float* out = (float*)d_out;

    const size_t smem_bytes = SMEM_FLOATS * sizeof(float);
    cudaFuncSetAttribute(gru_kernel, cudaFuncAttributeMaxDynamicSharedMemorySize,
                         (int)smem_bytes);
    gru_kernel<<<BB / MB, NTHREADS, smem_bytes>>>(x, w_ih, w_hh, b_ih, b_hh,
                                                  w_lin, b_lin, out);
}

// round 5
// speedup vs baseline: 1.0171x; 1.0171x over previous
#include <cuda_runtime.h>

// GRU_39170101739852: B=4096, T=512, H=64 GRU + Linear(H->1), fp32.
// R5: conflict-free interleaved W layout (coalesced LDS.128) + NB=8 W reuse.
// 128 threads/CTA, MB=16, grid=256 -> 2 CTAs/SM; FMA pipe becomes binding.

#define BB 4096
#define TT 512
#define HH 64
#define MB 16
#define NTHREADS 128
#define NB 8
#define TCHUNK 32

typedef unsigned long long u64;

__device__ __forceinline__ u64 pack2(float lo, float hi) {
    u64 r; asm("mov.b64 %0, {%1,%2};" : "=l"(r) : "f"(lo), "f"(hi)); return r;
}
__device__ __forceinline__ void unpack2(u64 v, float &lo, float &hi) {
    asm("mov.b64 {%0,%1}, %2;" : "=f"(lo), "=f"(hi) : "l"(v));
}
__device__ __forceinline__ void fma2(u64 &d, u64 a, u64 b) {
    asm("fma.rn.f32x2 %0, %1, %2, %0;" : "+l"(d) : "l"(a), "l"(b));
}
__device__ __forceinline__ float hsum2(u64 v) {
    float lo, hi; unpack2(v, lo, hi); return lo + hi;
}
__device__ __forceinline__ float fsig(float v) {
    float e; asm("ex2.approx.f32 %0, %1;" : "=f"(e) : "f"(v * -1.4426950408889634f));
    float r; asm("rcp.approx.f32 %0, %1;" : "=f"(r) : "f"(1.0f + e));
    return r;
}
__device__ __forceinline__ float ftanh(float v) {
    return fmaf(2.0f, fsig(2.0f * v), -1.0f);
}

// Shared layout (floats):
//   W   : [0, 12288)    u64-packed, idx ((g*2+uh)*16 + kq)*64 + 2*lane + p
//   hA  : [12288, +1024)  h buffer 0: h[b*64 + k]
//   hB  : [13312, +1024)  h buffer 1
//   xt  : [14336, +1024)  x tiles, 2 bufs of 16x32
//   red : [15360, +64)    out partials, 2 bufs of 16x2
#define OFF_HA 12288
#define OFF_HB 13312
#define OFF_X  14336
#define OFF_R  15360
#define SMEM_FLOATS 15424

__global__ void __launch_bounds__(NTHREADS, 2)
gru_kernel(const float* __restrict__ x,
           const float* __restrict__ w_ih,
           const float* __restrict__ w_hh,
           const float* __restrict__ b_ih,
           const float* __restrict__ b_hh,
           const float* __restrict__ w_lin,
           const float* __restrict__ b_lin,
           float* __restrict__ out)
{
    extern __shared__ float smem[];
    u64*   wsh = reinterpret_cast<u64*>(smem);   // 6144 u64
    float* hA  = smem + OFF_HA;
    float* hB  = smem + OFF_HB;
    float* xt  = smem + OFF_X;
    float* red = smem + OFF_R;

    const int tid  = threadIdx.x;
    const int u    = tid & 63;         // hidden unit
    const int bt   = tid >> 6;         // batch tile 0..1
    const int uh   = (tid >> 5) & 1;   // unit half
    const int lane = tid & 31;
    const int b0   = bt * NB;
    const int bg   = blockIdx.x * MB;

    // ---- pack W_hh into interleaved conflict-free layout ----
    // wsh[((g*2+uh)*16 + kq)*64 + 2*lane + p] = pack2(W[g][uu][4kq+2p], W[g][uu][4kq+2p+1])
    for (int idx = tid; idx < 6144; idx += NTHREADS) {
        const int p   = idx & 1;
        const int ln  = (idx >> 1) & 31;
        const int rst = idx >> 6;
        const int kq  = rst & 15;
        const int guh = rst >> 4;            // 0..5
        const int g   = guh >> 1;
        const int hh  = guh & 1;
        const int uu  = hh * 32 + ln;
        const float2 wv = *reinterpret_cast<const float2*>(
            &w_hh[(g * HH + uu) * HH + 4 * kq + 2 * p]);
        wsh[idx] = pack2(wv.x, wv.y);
    }
    for (int i = tid; i < 2048; i += NTHREADS) hA[i] = 0.0f;   // zeros hA+hB

    // Stage first x chunk: 16 rows x 32 t = 128 float4
    {
        int bl = tid >> 3, q = tid & 7;
        float4 v = *reinterpret_cast<const float4*>(&x[(size_t)(bg + bl) * TT + q * 4]);
        *reinterpret_cast<float4*>(&xt[bl * TCHUNK + q * 4]) = v;
    }

    const float wir = w_ih[u], wiz = w_ih[HH + u], win = w_ih[2 * HH + u];
    const float brc = b_ih[u]        + b_hh[u];
    const float bzc = b_ih[HH + u]   + b_hh[HH + u];
    const float bin = b_ih[2 * HH + u];
    const float bhn = b_hh[2 * HH + u];
    const float wlu = w_lin[u];
    const float blv = b_lin[0];

    const u64* wbase = wsh + uh * 1024 + 2 * lane;   // gate stride 2048, kq stride 64

    float hprev[NB];
    #pragma unroll
    for (int j = 0; j < NB; ++j) hprev[j] = 0.0f;

    __syncthreads();

    int p = 0;
    for (int t = 0; t < TT; ++t) {
        const float* hr = p ? hB : hA;
        float*       hw = p ? hA : hB;
        const float* hrow = hr + b0 * HH;

        // ---- GEMM: k-paired f32x2, coalesced W, broadcast h ----
        u64 ar[NB], az[NB], an[NB];
        #pragma unroll
        for (int j = 0; j < NB; ++j) { ar[j] = 0ull; az[j] = 0ull; an[j] = 0ull; }

        #pragma unroll
        for (int kq = 0; kq < 16; ++kq) {
            const ulonglong2 wr = *reinterpret_cast<const ulonglong2*>(wbase + kq * 64);
            const ulonglong2 wz = *reinterpret_cast<const ulonglong2*>(wbase + 2048 + kq * 64);
            const ulonglong2 wn = *reinterpret_cast<const ulonglong2*>(wbase + 4096 + kq * 64);
            ulonglong2 hp[NB];
            #pragma unroll
            for (int j = 0; j < NB; ++j)
                hp[j] = *reinterpret_cast<const ulonglong2*>(&hrow[j * HH + 4 * kq]);
            #pragma unroll
            for (int j = 0; j < NB; ++j) {
                fma2(ar[j], wr.x, hp[j].x); fma2(ar[j], wr.y, hp[j].y);
                fma2(az[j], wz.x, hp[j].x); fma2(az[j], wz.y, hp[j].y);
                fma2(an[j], wn.x, hp[j].x); fma2(an[j], wn.y, hp[j].y);
            }
        }

        // ---- Epilogue ----
        const int ttl = t & (TCHUNK - 1);
        const float* xcur = xt + ((t >> 5) & 1) * (MB * TCHUNK);
        float s[NB];
        #pragma unroll
        for (int j = 0; j < NB; ++j) {
            const float xv = xcur[(b0 + j) * TCHUNK + ttl];
            const float r  = fsig(fmaf(wir, xv, hsum2(ar[j]) + brc));
            const float z  = fsig(fmaf(wiz, xv, hsum2(az[j]) + bzc));
            const float n  = ftanh(fmaf(r, hsum2(an[j]) + bhn, fmaf(win, xv, bin)));
            const float hn = fmaf(z, hprev[j] - n, n);
            hprev[j] = hn;
            hw[(b0 + j) * HH + u] = hn;
            s[j] = wlu * hn;
        }

        // Reduce over 32 units of this warp's half
        #pragma unroll
        for (int off = 16; off; off >>= 1) {
            #pragma unroll
            for (int j = 0; j < NB; ++j)
                s[j] += __shfl_xor_sync(0xffffffffu, s[j], off);
        }
        float* rcur = red + (t & 1) * (MB * 2);
        if (lane == 0) {
            #pragma unroll
            for (int j = 0; j < NB; ++j)
                rcur[(b0 + j) * 2 + uh] = s[j];
        }

        // Stage next x chunk
        if (((t + 1) & (TCHUNK - 1)) == 0 && (t + 1) < TT) {
            int bl = tid >> 3, q = tid & 7;
            float4 v = *reinterpret_cast<const float4*>(
                &x[(size_t)(bg + bl) * TT + (t + 1) + q * 4]);
            float* xnext = xt + (((t + 1) >> 5) & 1) * (MB * TCHUNK);
            *reinterpret_cast<float4*>(&xnext[bl * TCHUNK + q * 4]) = v;
        }

        __syncthreads();

        if (tid < MB) {
            out[(size_t)(bg + tid) * TT + t] =
                rcur[tid * 2] + rcur[tid * 2 + 1] + blv;
        }
        p ^= 1;
    }
}

extern "C" void kernel_launch(void* const* d_in, const int* in_sizes, int n_in,
                              void* d_out, int out_size) {
    const float* x     = (const float*)d_in[0];
    const float* w_ih  = (const float*)d_in[1];
    const float* w_hh  = (const float*)d_in[2];
    const float* b_ih  = (const float*)d_in[3];
    const float* b_hh  = (const float*)d_in[4];
    const float* w_lin = (const float*)d_in[5];
    const float* b_lin = (const float*)d_in[6];
    float* out = (float*)d_out;

    const size_t smem_bytes = SMEM_FLOATS * sizeof(float);
    cudaFuncSetAttribute(gru_kernel, cudaFuncAttributeMaxDynamicSharedMemorySize,
                         (int)smem_bytes);
    gru_kernel<<<BB / MB, NTHREADS, smem_bytes>>>(x, w_ih, w_hh, b_ih, b_hh,
                                                  w_lin, b_lin, out);
}

// round 6
// speedup vs baseline: 1.0210x; 1.0039x over previous
#include <cuda_runtime.h>

// GRU_39170101739852: B=4096, T=512, H=64 GRU + Linear(H->1), fp32.
// R6: W_hh fully register-resident (2-way k-split, 96 regs), NB=16 via 4
// passes of 4 batches (12 u64 accs live), slot-permuted 2-way shuffle
// reduction, h_prev re-read from smem. 128 thr, MB=16, 2 CTAs/SM.

#define TT 512
#define HH 64
#define MB 16
#define NTHREADS 128
#define TCHUNK 32
#define PITCH_H 72      // h row: k at [k + 4*(k>=32)]; halves 128+16B apart

typedef unsigned long long u64;

__device__ __forceinline__ u64 pack2(float lo, float hi) {
    u64 r; asm("mov.b64 %0, {%1,%2};" : "=l"(r) : "f"(lo), "f"(hi)); return r;
}
__device__ __forceinline__ void unpack2(u64 v, float &lo, float &hi) {
    asm("mov.b64 {%0,%1}, %2;" : "=f"(lo), "=f"(hi) : "l"(v));
}
__device__ __forceinline__ void fma2(u64 &d, u64 a, u64 b) {
    asm("fma.rn.f32x2 %0, %1, %2, %0;" : "+l"(d) : "l"(a), "l"(b));
}
__device__ __forceinline__ void add2(u64 &d, u64 a) {
    asm("add.rn.f32x2 %0, %0, %1;" : "+l"(d) : "l"(a));
}
__device__ __forceinline__ float hsum2(u64 v) {
    float lo, hi; unpack2(v, lo, hi); return lo + hi;
}
__device__ __forceinline__ u64 shflx64_1(u64 v) {
    float lo, hi; unpack2(v, lo, hi);
    lo = __shfl_xor_sync(0xffffffffu, lo, 1);
    hi = __shfl_xor_sync(0xffffffffu, hi, 1);
    return pack2(lo, hi);
}
__device__ __forceinline__ float fsig(float v) {
    float e; asm("ex2.approx.f32 %0, %1;" : "=f"(e) : "f"(v * -1.4426950408889634f));
    float r; asm("rcp.approx.f32 %0, %1;" : "=f"(r) : "f"(1.0f + e));
    return r;
}
__device__ __forceinline__ float ftanh(float v) {
    return fmaf(2.0f, fsig(2.0f * v), -1.0f);
}

// Static smem (floats):
//   hA: [0,1152)  hB: [1152,2304)  (16 rows x pitch 72)
//   xt: [2304,+1024)  2 bufs of 16x32
//   red:[3328,+128)   2 bufs of 16x4
#define OFF_HB 1152
#define OFF_X  2304
#define OFF_R  3328
#define SMEM_FLOATS 3456

__global__ void __launch_bounds__(NTHREADS, 2)
gru_kernel(const float* __restrict__ x,
           const float* __restrict__ w_ih,
           const float* __restrict__ w_hh,
           const float* __restrict__ b_ih,
           const float* __restrict__ b_hh,
           const float* __restrict__ w_lin,
           const float* __restrict__ b_lin,
           float* __restrict__ out)
{
    __shared__ float smem[SMEM_FLOATS];
    float* hA  = smem;
    float* hB  = smem + OFF_HB;
    float* xt  = smem + OFF_X;
    float* red = smem + OFF_R;

    const int tid  = threadIdx.x;
    const int c    = tid & 1;          // k-half: k in [32c, 32c+32)
    const int u    = tid >> 1;         // hidden unit 0..63
    const int wrp  = tid >> 5;         // warp 0..3 (covers u = 16*wrp..+15)
    const int lane = tid & 31;
    const int cc2  = c << 1;
    const int bg   = blockIdx.x * MB;
    const int uoff = u + ((u >> 5) << 2);   // padded store offset

    // ---- W_hh into registers: 3 gates x 16 k-pairs (this thread's k-half) ----
    u64 wR[16], wZ[16], wN[16];
    {
        const float* pr = &w_hh[(0 * HH + u) * HH + 32 * c];
        const float* pz = &w_hh[(1 * HH + u) * HH + 32 * c];
        const float* pn = &w_hh[(2 * HH + u) * HH + 32 * c];
        #pragma unroll
        for (int i = 0; i < 16; ++i) {
            float2 a = *reinterpret_cast<const float2*>(pr + 2 * i);
            float2 b = *reinterpret_cast<const float2*>(pz + 2 * i);
            float2 d = *reinterpret_cast<const float2*>(pn + 2 * i);
            wR[i] = pack2(a.x, a.y);
            wZ[i] = pack2(b.x, b.y);
            wN[i] = pack2(d.x, d.y);
        }
    }

    for (int i = tid; i < 2 * OFF_HB; i += NTHREADS) hA[i] = 0.0f;  // hA+hB

    // Stage first x chunk: 16 rows x 32 t = 128 float4
    {
        int bl = tid >> 3, q = tid & 7;
        float4 v = *reinterpret_cast<const float4*>(&x[(size_t)(bg + bl) * TT + q * 4]);
        *reinterpret_cast<float4*>(&xt[bl * TCHUNK + q * 4]) = v;
    }

    const float wir = w_ih[u], wiz = w_ih[HH + u], win = w_ih[2 * HH + u];
    const float brc = b_ih[u]        + b_hh[u];
    const float bzc = b_ih[HH + u]   + b_hh[HH + u];
    const float bin = b_ih[2 * HH + u];
    const float bhn = b_hh[2 * HH + u];
    const float wlu = w_lin[u];
    const float blv = b_lin[0];

    __syncthreads();

    int p = 0;
    for (int t = 0; t < TT; ++t) {
        const float* hr = p ? hB : hA;
        float*       hw = p ? hA : hB;
        const int   ttl  = t & (TCHUNK - 1);
        const float* xcur = xt + ((t >> 5) & 1) * (MB * TCHUNK);
        float* rcur = red + (t & 1) * 64;

        #pragma unroll 1
        for (int j0 = 0; j0 < MB; j0 += 4) {
            // slot s reads batch j0 + (s ^ cc2), this thread's k-half
            const float* r0 = hr + (j0 + (0 ^ cc2)) * PITCH_H + c * 36;
            const float* r1 = hr + (j0 + (1 ^ cc2)) * PITCH_H + c * 36;
            const float* r2 = hr + (j0 + (2 ^ cc2)) * PITCH_H + c * 36;
            const float* r3 = hr + (j0 + (3 ^ cc2)) * PITCH_H + c * 36;

            u64 ar[4] = {0,0,0,0}, az[4] = {0,0,0,0}, an[4] = {0,0,0,0};

            #pragma unroll
            for (int q = 0; q < 8; ++q) {
                ulonglong2 h0 = *reinterpret_cast<const ulonglong2*>(r0 + 4 * q);
                ulonglong2 h1 = *reinterpret_cast<const ulonglong2*>(r1 + 4 * q);
                ulonglong2 h2 = *reinterpret_cast<const ulonglong2*>(r2 + 4 * q);
                ulonglong2 h3 = *reinterpret_cast<const ulonglong2*>(r3 + 4 * q);
                const u64 wa = wR[2*q], wb = wR[2*q+1];
                const u64 za = wZ[2*q], zb = wZ[2*q+1];
                const u64 na = wN[2*q], nb = wN[2*q+1];
                fma2(ar[0], wa, h0.x); fma2(ar[0], wb, h0.y);
                fma2(az[0], za, h0.x); fma2(az[0], zb, h0.y);
                fma2(an[0], na, h0.x); fma2(an[0], nb, h0.y);
                fma2(ar[1], wa, h1.x); fma2(ar[1], wb, h1.y);
                fma2(az[1], za, h1.x); fma2(az[1], zb, h1.y);
                fma2(an[1], na, h1.x); fma2(an[1], nb, h1.y);
                fma2(ar[2], wa, h2.x); fma2(ar[2], wb, h2.y);
                fma2(az[2], za, h2.x); fma2(az[2], zb, h2.y);
                fma2(an[2], na, h2.x); fma2(an[2], nb, h2.y);
                fma2(ar[3], wa, h3.x); fma2(ar[3], wb, h3.y);
                fma2(az[3], za, h3.x); fma2(az[3], zb, h3.y);
                fma2(an[3], na, h3.x); fma2(an[3], nb, h3.y);
            }

            // 2-way k-half reduction: res[e] = acc[e] + partner's acc[e+2]
            add2(ar[0], shflx64_1(ar[2])); add2(ar[1], shflx64_1(ar[3]));
            add2(az[0], shflx64_1(az[2])); add2(az[1], shflx64_1(az[3]));
            add2(an[0], shflx64_1(an[2])); add2(an[1], shflx64_1(an[3]));

            // epilogue: this lane owns batches j0 + 2c + {0,1}
            float sv[2];
            #pragma unroll
            for (int e = 0; e < 2; ++e) {
                const int jb = j0 + cc2 + e;
                const float rs = (e ? hsum2(ar[1]) : hsum2(ar[0])) + brc;
                const float zs = (e ? hsum2(az[1]) : hsum2(az[0])) + bzc;
                const float ns = (e ? hsum2(an[1]) : hsum2(an[0])) + bhn;
                const float xv = xcur[jb * TCHUNK + ttl];
                const float hpv = hr[jb * PITCH_H + uoff];
                const float rg = fsig(fmaf(wir, xv, rs));
                const float zg = fsig(fmaf(wiz, xv, zs));
                const float ng = ftanh(fmaf(rg, ns, fmaf(win, xv, bin)));
                const float hn = fmaf(zg, hpv - ng, ng);
                hw[jb * PITCH_H + uoff] = hn;
                sv[e] = wlu * hn;
            }

            // output dot: sum over this warp's 16 units
            #pragma unroll
            for (int off = 2; off <= 16; off <<= 1) {
                sv[0] += __shfl_xor_sync(0xffffffffu, sv[0], off);
                sv[1] += __shfl_xor_sync(0xffffffffu, sv[1], off);
            }
            if ((lane & 30) == 0) {           // lanes 0 (c=0) and 1 (c=1)
                rcur[(j0 + cc2 + 0) * 4 + wrp] = sv[0];
                rcur[(j0 + cc2 + 1) * 4 + wrp] = sv[1];
            }
        }

        // Stage next x chunk before the barrier
        if (((t + 1) & (TCHUNK - 1)) == 0 && (t + 1) < TT) {
            int bl = tid >> 3, q = tid & 7;
            float4 v = *reinterpret_cast<const float4*>(
                &x[(size_t)(bg + bl) * TT + (t + 1) + q * 4]);
            float* xnext = xt + (((t + 1) >> 5) & 1) * (MB * TCHUNK);
            *reinterpret_cast<float4*>(&xnext[bl * TCHUNK + q * 4]) = v;
        }

        __syncthreads();

        if (tid < MB) {
            const float4 r4 = *reinterpret_cast<const float4*>(&rcur[tid * 4]);
            out[(size_t)(bg + tid) * TT + t] = (r4.x + r4.y) + (r4.z + r4.w) + blv;
        }
        p ^= 1;
    }
}

extern "C" void kernel_launch(void* const* d_in, const int* in_sizes, int n_in,
                              void* d_out, int out_size) {
    const float* x     = (const float*)d_in[0];
    const float* w_ih  = (const float*)d_in[1];
    const float* w_hh  = (const float*)d_in[2];
    const float* b_ih  = (const float*)d_in[3];
    const float* b_hh  = (const float*)d_in[4];
    const float* w_lin = (const float*)d_in[5];
    const float* b_lin = (const float*)d_in[6];
    float* out = (float*)d_out;

    gru_kernel<<<4096 / MB, NTHREADS>>>(x, w_ih, w_hh, b_ih, b_hh,
                                        w_lin, b_lin, out);
}